// round 10
// baseline (speedup 1.0000x reference)
#include <cuda_runtime.h>
#include <cuda_bf16.h>
#include <cuda_fp16.h>
#include <math.h>

#define LQ     9216
#define NBATCH 2
#define M_TOT  (NBATCH * LQ)     // 18432
#define CH     256
#define HEADS  8
#define NP     25
#define DH     32
#define HID    1024
#define NQP    896               // [val 256 | off 400 | logit 200 | pad 40]
#define OFF_COL  256
#define LOG_COL  656

#define TBL      (NBATCH * HEADS * LQ * DH)
#define TBLBYTES (TBL * 2)

#define WQ_N   (CH * NQP)                 // 229376
#define W2_N   (CH * CH)                  // 65536
#define W3_N   (CH * HID)                 // 262144
#define W4_N   (HID * CH)                 // 262144

// ---------------- scratch ----------------
__device__ __nv_bfloat16 g_qh   [M_TOT * CH];
__device__ float         g_proj [M_TOT * NQP];
__device__ __align__(128) __nv_bfloat16 g_valh[2 * TBL + 96];
__device__ __nv_bfloat16 g_attnh[M_TOT * CH];
__device__ float         g_x1   [M_TOT * CH];
__device__ __nv_bfloat16 g_yh   [M_TOT * CH];
__device__ __nv_bfloat16 g_h1h  [M_TOT * HID];
__device__ __nv_bfloat16 g_wqh  [CH * NQP];
__device__ float         g_bq   [NQP];
__device__ __nv_bfloat16 g_wouth[CH * CH];
__device__ __nv_bfloat16 g_wfc1h[CH * HID];
__device__ __nv_bfloat16 g_wfc2h[HID * CH];

__device__ __forceinline__ void cp16(void* s, const void* g) {
    unsigned sa = (unsigned)__cvta_generic_to_shared(s);
    asm volatile("cp.async.cg.shared.global [%0], [%1], 16;\n" :: "r"(sa), "l"(g));
}

__device__ __forceinline__ void mma_bf16(float c[4], unsigned a0, unsigned a1,
                                         unsigned a2, unsigned a3,
                                         unsigned b0, unsigned b1) {
    asm volatile(
        "mma.sync.aligned.m16n8k16.row.col.f32.bf16.bf16.f32 "
        "{%0,%1,%2,%3},{%4,%5,%6,%7},{%8,%9},{%0,%1,%2,%3};\n"
        : "+f"(c[0]), "+f"(c[1]), "+f"(c[2]), "+f"(c[3])
        : "r"(a0), "r"(a1), "r"(a2), "r"(a3), "r"(b0), "r"(b1));
}

__device__ __forceinline__ void ldsm_x4(unsigned r[4], unsigned addr) {
    asm volatile("ldmatrix.sync.aligned.m8n8.x4.shared.b16 {%0,%1,%2,%3}, [%4];"
                 : "=r"(r[0]), "=r"(r[1]), "=r"(r[2]), "=r"(r[3]) : "r"(addr));
}
__device__ __forceinline__ void ldsm_x4t(unsigned r[4], unsigned addr) {
    asm volatile("ldmatrix.sync.aligned.m8n8.x4.trans.shared.b16 {%0,%1,%2,%3}, [%4];"
                 : "=r"(r[0]), "=r"(r[1]), "=r"(r[2]), "=r"(r[3]) : "r"(addr));
}

__device__ __forceinline__ float2 bf2f2(unsigned v) {
    float2 r;
    r.x = __uint_as_float(v << 16);
    r.y = __uint_as_float(v & 0xffff0000u);
    return r;
}

// ---------------- single prep kernel: fuse q-weights + convert all weights ----
__global__ void prep_all(const float* __restrict__ w_val, const float* __restrict__ w_off,
                         const float* __restrict__ w_attn, const float* __restrict__ b_val,
                         const float* __restrict__ b_off, const float* __restrict__ b_attn,
                         const float* __restrict__ w_out, const float* __restrict__ w_fc1,
                         const float* __restrict__ w_fc2,
                         __nv_bfloat16* __restrict__ wq, float* __restrict__ bq,
                         __nv_bfloat16* __restrict__ d_out, __nv_bfloat16* __restrict__ d_fc1,
                         __nv_bfloat16* __restrict__ d_fc2) {
    int i = blockIdx.x * blockDim.x + threadIdx.x;
    if (i < WQ_N) {
        int row = i / NQP, col = i - row * NQP;
        float v;
        if      (col < 256) v = w_val [row * 256 + col];
        else if (col < 656) v = w_off [row * 400 + (col - 256)];
        else if (col < 856) v = w_attn[row * 200 + (col - 656)];
        else                v = 0.f;
        wq[i] = __float2bfloat16(v);
        if (row == 0) {
            float b;
            if      (col < 256) b = b_val [col];
            else if (col < 656) b = b_off [col - 256];
            else if (col < 856) b = b_attn[col - 656];
            else                b = 0.f;
            bq[col] = b;
        }
    } else if (i < WQ_N + W2_N) {
        int j = i - WQ_N;
        d_out[j] = __float2bfloat16(w_out[j]);
    } else if (i < WQ_N + W2_N + W3_N) {
        int j = i - WQ_N - W2_N;
        d_fc1[j] = __float2bfloat16(w_fc1[j]);
    } else if (i < WQ_N + W2_N + W3_N + W4_N) {
        int j = i - WQ_N - W2_N - W3_N;
        d_fc2[j] = __float2bfloat16(w_fc2[j]);
    }
}

// ---------------- LayerNorm (warp/row), bf16 output ----------------
__global__ void ln_kernel(const float* __restrict__ x, const float* __restrict__ g,
                          const float* __restrict__ b, __nv_bfloat16* __restrict__ out) {
    int row  = blockIdx.x * blockDim.y + threadIdx.y;
    int lane = threadIdx.x;
    const float* xr = x + (size_t)row * CH;
    float v[8], s = 0.f, sq = 0.f;
#pragma unroll
    for (int i = 0; i < 8; i++) {
        v[i] = xr[lane + 32 * i];
        s += v[i]; sq += v[i] * v[i];
    }
#pragma unroll
    for (int o = 16; o > 0; o >>= 1) {
        s  += __shfl_xor_sync(0xffffffffu, s,  o);
        sq += __shfl_xor_sync(0xffffffffu, sq, o);
    }
    float mean = s * (1.f / 256.f);
    float var  = sq * (1.f / 256.f) - mean * mean;
    float rstd = rsqrtf(var + 1e-5f);
    __nv_bfloat16* outr = out + (size_t)row * CH;
#pragma unroll
    for (int i = 0; i < 8; i++) {
        int c = lane + 32 * i;
        outr[c] = __float2bfloat16((v[i] - mean) * rstd * g[c] + b[c]);
    }
}

// ---------------- bf16 tensor-core GEMM (unchanged from R9) ----------------
#define ALD2 56
#define BLD2 136
#define A_ST2 (128 * ALD2)
#define B_ST2 (32 * BLD2)
#define GSMEM ((3 * (A_ST2 + B_ST2)) * 2)

__global__ void __launch_bounds__(256, 2)
gemm_bf16(const __nv_bfloat16* __restrict__ A, const __nv_bfloat16* __restrict__ B,
          const float* __restrict__ bias, const float* __restrict__ R,
          float* __restrict__ C, __nv_bfloat16* __restrict__ H,
          int M, int N, int K, int epi) {
    extern __shared__ __nv_bfloat16 sm2[];
    __nv_bfloat16* Asm = sm2;
    __nv_bfloat16* Bsm = sm2 + 3 * A_ST2;

    int tid = threadIdx.x, lane = tid & 31, warp = tid >> 5;
    int wr = warp >> 1, wc = warp & 1;
    int row0 = blockIdx.y * 128, col0 = blockIdx.x * 128;
    int gID = lane >> 2, tig = lane & 3;

    float acc[2][8][4] = {};
    int ntile = K / 32;

    int a_off = (wr * 32 + (lane & 15)) * ALD2 + ((lane >> 4) & 1) * 8;
    int b_off = (lane & 15) * BLD2 + wc * 64 + ((lane >> 4) & 1) * 8;
    unsigned smem_base = (unsigned)__cvta_generic_to_shared(sm2);
    unsigned aAddr[3], bAddr[3];
#pragma unroll
    for (int s = 0; s < 3; s++) {
        aAddr[s] = smem_base + (s * A_ST2 + a_off) * 2;
        bAddr[s] = smem_base + ((3 * A_ST2) + s * B_ST2 + b_off) * 2;
    }

#define LOAD_STAGE(st, t)                                                       \
    {                                                                           \
        __nv_bfloat16* as = Asm + (st) * A_ST2;                                 \
        _Pragma("unroll")                                                       \
        for (int i = 0; i < 2; i++) {                                           \
            int id = tid + i * 256;                                             \
            int r = id >> 2, c8 = (id & 3) * 8;                                 \
            cp16(&as[r * ALD2 + c8], A + (size_t)(row0 + r) * K + (t) * 32 + c8); \
        }                                                                       \
        __nv_bfloat16* bs = Bsm + (st) * B_ST2;                                 \
        _Pragma("unroll")                                                       \
        for (int i = 0; i < 2; i++) {                                           \
            int id = tid + i * 256;                                             \
            int r = id >> 4, c = (id & 15) * 8;                                 \
            cp16(&bs[r * BLD2 + c], B + (size_t)((t) * 32 + r) * N + col0 + c); \
        }                                                                       \
    }

    LOAD_STAGE(0, 0);
    asm volatile("cp.async.commit_group;\n");
    LOAD_STAGE(1, 1);
    asm volatile("cp.async.commit_group;\n");

    for (int t = 0; t < ntile; t++) {
        asm volatile("cp.async.wait_group 1;\n");
        __syncthreads();
        if (t + 2 < ntile) LOAD_STAGE((t + 2) % 3, t + 2);
        asm volatile("cp.async.commit_group;\n");

        int s = t % 3;
#pragma unroll
        for (int step = 0; step < 2; step++) {
            unsigned Af[2][4], Bf[4][4];
#pragma unroll
            for (int mt = 0; mt < 2; mt++)
                ldsm_x4(Af[mt], aAddr[s] + (mt * 16 * ALD2 + step * 16) * 2);
#pragma unroll
            for (int nb = 0; nb < 4; nb++)
                ldsm_x4t(Bf[nb], bAddr[s] + (step * 16 * BLD2 + nb * 16) * 2);
#pragma unroll
            for (int nb = 0; nb < 4; nb++) {
#pragma unroll
                for (int mt = 0; mt < 2; mt++) {
                    mma_bf16(acc[mt][2 * nb],     Af[mt][0], Af[mt][1], Af[mt][2], Af[mt][3], Bf[nb][0], Bf[nb][1]);
                    mma_bf16(acc[mt][2 * nb + 1], Af[mt][0], Af[mt][1], Af[mt][2], Af[mt][3], Bf[nb][2], Bf[nb][3]);
                }
            }
        }
    }

#pragma unroll
    for (int mt = 0; mt < 2; mt++) {
#pragma unroll
        for (int nt = 0; nt < 8; nt++) {
            int row = row0 + wr * 32 + mt * 16 + gID;
            int col = col0 + wc * 64 + nt * 8 + tig * 2;
            if (epi == 3 && col >= 856) continue;
            float b0 = bias[col], b1 = bias[col + 1];
            float v0 = acc[mt][nt][0] + b0;
            float v1 = acc[mt][nt][1] + b1;
            float v2 = acc[mt][nt][2] + b0;
            float v3 = acc[mt][nt][3] + b1;
            if (epi == 1) {
                v0 = 0.5f * v0 * (1.f + erff(v0 * 0.70710678118654752440f));
                v1 = 0.5f * v1 * (1.f + erff(v1 * 0.70710678118654752440f));
                v2 = 0.5f * v2 * (1.f + erff(v2 * 0.70710678118654752440f));
                v3 = 0.5f * v3 * (1.f + erff(v3 * 0.70710678118654752440f));
                *(__nv_bfloat162*)(H + (size_t)row * N + col) = __floats2bfloat162_rn(v0, v1);
                *(__nv_bfloat162*)(H + (size_t)(row + 8) * N + col) = __floats2bfloat162_rn(v2, v3);
            } else if (epi == 3 && col < 256) {
                int h  = col >> 5, dh = col & 31;
                int n_ = row / LQ, pix = row - n_ * LQ;
                __nv_bfloat16* d0 = H + ((size_t)(n_ * HEADS + h) * LQ + pix) * DH + dh;
                __nv_bfloat162 lohi  = __floats2bfloat162_rn(v0, v1);
                __nv_bfloat162 lohi2 = __floats2bfloat162_rn(v2, v3);
                *(__nv_bfloat162*)d0 = lohi;
                *(__nv_bfloat162*)(d0 + (size_t)8 * DH) = lohi2;
                __nv_bfloat16* d1 = d0 + (TBL + 32);
                *(__nv_bfloat162*)d1 = lohi;
                *(__nv_bfloat162*)(d1 + (size_t)8 * DH) = lohi2;
            } else {
                if (epi == 2) {
                    const float* r0 = R + (size_t)row * N + col;
                    const float* r1 = R + (size_t)(row + 8) * N + col;
                    v0 += r0[0]; v1 += r0[1]; v2 += r1[0]; v3 += r1[1];
                }
                float* d0 = C + (size_t)row * N + col;
                float* d1 = C + (size_t)(row + 8) * N + col;
                d0[0] = v0; d0[1] = v1; d1[0] = v2; d1[1] = v3;
            }
        }
    }
}

// ---------------- fused softmax + deformable bilinear attention ----------------
// Per-point params packed into ONE float4 {o0:int, o1:int, w0:half2(lo,hi),
// w1:half2(lo,hi)} -> single LDS.128 broadcast per point. Hot loop L1 traffic:
// 1 LDS wavefront + 2 aligned LDG wavefronts per point.
__global__ void deform_kernel(const __nv_bfloat16* __restrict__ valh,
                              const float* __restrict__ proj,
                              const float* __restrict__ refp,
                              __nv_bfloat16* __restrict__ out) {
    __shared__ float4 sP[HEADS][NP + 1];

    int bq   = blockIdx.x;
    int n    = bq / LQ;
    int h    = threadIdx.y;
    int lane = threadIdx.x;

    const float* rowp = proj + (size_t)bq * NQP;
    const float* logr = rowp + LOG_COL + h * NP;

    float lg = (lane < NP) ? logr[lane] : -1e30f;
    float mx = lg;
#pragma unroll
    for (int o = 16; o > 0; o >>= 1) mx = fmaxf(mx, __shfl_xor_sync(0xffffffffu, mx, o));
    float e = (lane < NP) ? expf(lg - mx) : 0.f;
    float sum = e;
#pragma unroll
    for (int o = 16; o > 0; o >>= 1) sum += __shfl_xor_sync(0xffffffffu, sum, o);
    float awn = e / sum;

    if (lane < NP) {
        const float* offr = rowp + OFF_COL + h * (NP * 2);
        float rx = refp[(size_t)bq * 2 + 0];
        float ry = refp[(size_t)bq * 2 + 1];
        float gx = fmaf(rx, 96.f, offr[2 * lane]     - 0.5f);
        float gy = fmaf(ry, 96.f, offr[2 * lane + 1] - 0.5f);
        float x0f = floorf(gx), y0f = floorf(gy);
        float fx = gx - x0f, fy = gy - y0f;
        int x0 = (int)x0f, y0 = (int)y0f;
        int x1 = x0 + 1,   y1 = y0 + 1;
        int px = min(max(x0, 0), 95);
        float wx0 = (x0 >= 0 && x0 < 96) ? (1.f - fx) : 0.f;
        float wx1 = (x1 >= 0 && x1 < 96) ? fx : 0.f;
        bool at0 = (px == x0);
        float wlo = at0 ? wx0 : wx1;
        float whi = at0 ? wx1 : 0.f;
        float wy0 = (y0 >= 0 && y0 < 96) ? (1.f - fy) : 0.f;
        float wy1 = (y1 >= 0 && y1 < 96) ? fy : 0.f;
        int ry0 = min(max(y0, 0), 95);
        int ry1 = min(max(y1, 0), 95);
        int tb = (px & 1) ? (TBLBYTES + 64) : 0;
        int o0 = tb + (ry0 * 96 + px) * (DH * 2);
        int o1 = tb + (ry1 * 96 + px) * (DH * 2);
        __half2 w0 = __floats2half2_rn(wy0 * wlo * awn, wy0 * whi * awn);
        __half2 w1 = __floats2half2_rn(wy1 * wlo * awn, wy1 * whi * awn);
        sP[h][lane] = make_float4(__int_as_float(o0), __int_as_float(o1),
                                  __uint_as_float(*(unsigned*)&w0),
                                  __uint_as_float(*(unsigned*)&w1));
    }
    __syncwarp();

    const char* vb = (const char*)(valh + (size_t)(n * HEADS + h) * LQ * DH) + lane * 4;
    bool lo = (lane < 16);

    float accx = 0.f, accy = 0.f;
#pragma unroll
    for (int p = 0; p < NP; p++) {
        float4 q = sP[h][p];
        int b0 = __float_as_int(q.x);
        int b1 = __float_as_int(q.y);
        unsigned w0b = __float_as_uint(q.z);
        unsigned w1b = __float_as_uint(q.w);
        __half2 w0 = *(__half2*)&w0b;
        __half2 w1 = *(__half2*)&w1b;
        float a0 = lo ? __low2float(w0) : __high2float(w0);
        float a1 = lo ? __low2float(w1) : __high2float(w1);
        float2 v0 = bf2f2(*(const unsigned*)(vb + b0));
        float2 v1 = bf2f2(*(const unsigned*)(vb + b1));
        accx = fmaf(a0, v0.x, accx);
        accy = fmaf(a0, v0.y, accy);
        accx = fmaf(a1, v1.x, accx);
        accy = fmaf(a1, v1.y, accy);
    }
    accx += __shfl_xor_sync(0xffffffffu, accx, 16);
    accy += __shfl_xor_sync(0xffffffffu, accy, 16);

    if (lo) {
        *(__nv_bfloat162*)(out + (size_t)bq * CH + h * DH + lane * 2) =
            __floats2bfloat162_rn(accx, accy);
    }
}

// ---------------- launch ----------------
extern "C" void kernel_launch(void* const* d_in, const int* in_sizes, int n_in,
                              void* d_out, int out_size) {
    const float* x      = (const float*)d_in[0];
    const float* refp   = (const float*)d_in[1];
    const float* ln1_g  = (const float*)d_in[4];
    const float* ln1_b  = (const float*)d_in[5];
    const float* w_off  = (const float*)d_in[6];
    const float* b_off  = (const float*)d_in[7];
    const float* w_attn = (const float*)d_in[8];
    const float* b_attn = (const float*)d_in[9];
    const float* w_val  = (const float*)d_in[10];
    const float* b_val  = (const float*)d_in[11];
    const float* w_out  = (const float*)d_in[12];
    const float* b_out  = (const float*)d_in[13];
    const float* ln2_g  = (const float*)d_in[14];
    const float* ln2_b  = (const float*)d_in[15];
    const float* w_fc1  = (const float*)d_in[16];
    const float* b_fc1  = (const float*)d_in[17];
    const float* w_fc2  = (const float*)d_in[18];
    const float* b_fc2  = (const float*)d_in[19];
    float* out = (float*)d_out;

    float *p_proj, *p_x1, *p_bq;
    __nv_bfloat16 *p_qh, *p_valh, *p_attnh, *p_yh, *p_h1h;
    __nv_bfloat16 *p_wqh, *p_wouth, *p_wfc1h, *p_wfc2h;
    cudaGetSymbolAddress((void**)&p_qh,    g_qh);
    cudaGetSymbolAddress((void**)&p_proj,  g_proj);
    cudaGetSymbolAddress((void**)&p_valh,  g_valh);
    cudaGetSymbolAddress((void**)&p_attnh, g_attnh);
    cudaGetSymbolAddress((void**)&p_x1,    g_x1);
    cudaGetSymbolAddress((void**)&p_yh,    g_yh);
    cudaGetSymbolAddress((void**)&p_h1h,   g_h1h);
    cudaGetSymbolAddress((void**)&p_wqh,   g_wqh);
    cudaGetSymbolAddress((void**)&p_bq,    g_bq);
    cudaGetSymbolAddress((void**)&p_wouth, g_wouth);
    cudaGetSymbolAddress((void**)&p_wfc1h, g_wfc1h);
    cudaGetSymbolAddress((void**)&p_wfc2h, g_wfc2h);

    static bool attr_done = false;
    if (!attr_done) {
        cudaFuncSetAttribute(gemm_bf16, cudaFuncAttributeMaxDynamicSharedMemorySize, GSMEM);
        attr_done = true;
    }

    int prep_total = WQ_N + W2_N + W3_N + W4_N;
    prep_all<<<(prep_total + 255) / 256, 256>>>(
        w_val, w_off, w_attn, b_val, b_off, b_attn, w_out, w_fc1, w_fc2,
        p_wqh, p_bq, p_wouth, p_wfc1h, p_wfc2h);

    dim3 lnBlock(32, 8);
    int  lnGrid = M_TOT / 8;

    // 1) LN1 -> bf16 q
    ln_kernel<<<lnGrid, lnBlock>>>(x, ln1_g, ln1_b, p_qh);
    // 2) fused q-projection: value -> dual bf16 tables, off/logit -> fp32
    gemm_bf16<<<dim3(NQP / 128, M_TOT / 128), 256, GSMEM>>>(
        p_qh, p_wqh, p_bq, nullptr, p_proj, p_valh, M_TOT, NQP, CH, 3);
    // 3) deform attention -> bf16
    deform_kernel<<<M_TOT, dim3(32, 8)>>>(p_valh, p_proj, refp, p_attnh);
    // 4) x1 = x + attn @ w_out + b_out (fp32)
    gemm_bf16<<<dim3(CH / 128, M_TOT / 128), 256, GSMEM>>>(
        p_attnh, p_wouth, b_out, x, p_x1, nullptr, M_TOT, CH, CH, 2);
    // 5) LN2 -> bf16 y
    ln_kernel<<<lnGrid, lnBlock>>>(p_x1, ln2_g, ln2_b, p_yh);
    // 6) h1 = gelu(y @ w_fc1 + b_fc1) -> bf16
    gemm_bf16<<<dim3(HID / 128, M_TOT / 128), 256, GSMEM>>>(
        p_yh, p_wfc1h, b_fc1, nullptr, nullptr, p_h1h, M_TOT, HID, CH, 1);
    // 7) out = x1 + h1 @ w_fc2 + b_fc2 (fp32)
    gemm_bf16<<<dim3(CH / 128, M_TOT / 128), 256, GSMEM>>>(
        p_h1h, p_wfc2h, b_fc2, p_x1, out, nullptr, M_TOT, CH, HID, 2);
}

// round 13
// speedup vs baseline: 1.0404x; 1.0404x over previous
#include <cuda_runtime.h>
#include <cuda_bf16.h>
#include <math.h>

#define LQ     9216
#define NBATCH 2
#define M_TOT  (NBATCH * LQ)     // 18432
#define CH     256
#define HEADS  8
#define NP     25
#define DH     32
#define HID    1024
#define NQP    896               // [val 256 | off 400 | logit 200 | pad 40]
#define OFF_COL  256
#define LOG_COL  656

#define TBL      (NBATCH * HEADS * LQ * DH)
#define TBLBYTES (TBL * 2)

#define WQ_N   (CH * NQP)
#define W2_N   (CH * CH)
#define W3_N   (CH * HID)
#define W4_N   (HID * CH)

// ---------------- scratch ----------------
__device__ __nv_bfloat16 g_qh   [M_TOT * CH];
__device__ float         g_proj [M_TOT * NQP];
__device__ __align__(128) __nv_bfloat16 g_valh[2 * TBL + 96];
__device__ __nv_bfloat16 g_attnh[M_TOT * CH];
__device__ float         g_x1   [M_TOT * CH];
__device__ __nv_bfloat16 g_yh   [M_TOT * CH];
__device__ __nv_bfloat16 g_h1h  [M_TOT * HID];
__device__ __nv_bfloat16 g_wqh  [CH * NQP];
__device__ float         g_bq   [NQP];
__device__ __nv_bfloat16 g_wouth[CH * CH];
__device__ __nv_bfloat16 g_wfc1h[CH * HID];
__device__ __nv_bfloat16 g_wfc2h[HID * CH];

__device__ __forceinline__ void cp16(void* s, const void* g) {
    unsigned sa = (unsigned)__cvta_generic_to_shared(s);
    asm volatile("cp.async.cg.shared.global [%0], [%1], 16;\n" :: "r"(sa), "l"(g));
}

__device__ __forceinline__ void mma_bf16(float c[4], unsigned a0, unsigned a1,
                                         unsigned a2, unsigned a3,
                                         unsigned b0, unsigned b1) {
    asm volatile(
        "mma.sync.aligned.m16n8k16.row.col.f32.bf16.bf16.f32 "
        "{%0,%1,%2,%3},{%4,%5,%6,%7},{%8,%9},{%0,%1,%2,%3};\n"
        : "+f"(c[0]), "+f"(c[1]), "+f"(c[2]), "+f"(c[3])
        : "r"(a0), "r"(a1), "r"(a2), "r"(a3), "r"(b0), "r"(b1));
}

__device__ __forceinline__ void ldsm_x4(unsigned r[4], unsigned addr) {
    asm volatile("ldmatrix.sync.aligned.m8n8.x4.shared.b16 {%0,%1,%2,%3}, [%4];"
                 : "=r"(r[0]), "=r"(r[1]), "=r"(r[2]), "=r"(r[3]) : "r"(addr));
}
__device__ __forceinline__ void ldsm_x4t(unsigned r[4], unsigned addr) {
    asm volatile("ldmatrix.sync.aligned.m8n8.x4.trans.shared.b16 {%0,%1,%2,%3}, [%4];"
                 : "=r"(r[0]), "=r"(r[1]), "=r"(r[2]), "=r"(r[3]) : "r"(addr));
}

// ---------------- single prep kernel ----------------
__global__ void prep_all(const float* __restrict__ w_val, const float* __restrict__ w_off,
                         const float* __restrict__ w_attn, const float* __restrict__ b_val,
                         const float* __restrict__ b_off, const float* __restrict__ b_attn,
                         const float* __restrict__ w_out, const float* __restrict__ w_fc1,
                         const float* __restrict__ w_fc2,
                         __nv_bfloat16* __restrict__ wq, float* __restrict__ bq,
                         __nv_bfloat16* __restrict__ d_out, __nv_bfloat16* __restrict__ d_fc1,
                         __nv_bfloat16* __restrict__ d_fc2) {
    int i = blockIdx.x * blockDim.x + threadIdx.x;
    if (i < WQ_N) {
        int row = i / NQP, col = i - row * NQP;
        float v;
        if      (col < 256) v = w_val [row * 256 + col];
        else if (col < 656) v = w_off [row * 400 + (col - 256)];
        else if (col < 856) v = w_attn[row * 200 + (col - 656)];
        else                v = 0.f;
        wq[i] = __float2bfloat16(v);
        if (row == 0) {
            float b;
            if      (col < 256) b = b_val [col];
            else if (col < 656) b = b_off [col - 256];
            else if (col < 856) b = b_attn[col - 656];
            else                b = 0.f;
            bq[col] = b;
        }
    } else if (i < WQ_N + W2_N) {
        int j = i - WQ_N;
        d_out[j] = __float2bfloat16(w_out[j]);
    } else if (i < WQ_N + W2_N + W3_N) {
        int j = i - WQ_N - W2_N;
        d_fc1[j] = __float2bfloat16(w_fc1[j]);
    } else if (i < WQ_N + W2_N + W3_N + W4_N) {
        int j = i - WQ_N - W2_N - W3_N;
        d_fc2[j] = __float2bfloat16(w_fc2[j]);
    }
}

// ---------------- LayerNorm (warp/row), bf16 output ----------------
__global__ void ln_kernel(const float* __restrict__ x, const float* __restrict__ g,
                          const float* __restrict__ b, __nv_bfloat16* __restrict__ out) {
    int row  = blockIdx.x * blockDim.y + threadIdx.y;
    int lane = threadIdx.x;
    const float* xr = x + (size_t)row * CH;
    float v[8], s = 0.f, sq = 0.f;
#pragma unroll
    for (int i = 0; i < 8; i++) {
        v[i] = xr[lane + 32 * i];
        s += v[i]; sq += v[i] * v[i];
    }
#pragma unroll
    for (int o = 16; o > 0; o >>= 1) {
        s  += __shfl_xor_sync(0xffffffffu, s,  o);
        sq += __shfl_xor_sync(0xffffffffu, sq, o);
    }
    float mean = s * (1.f / 256.f);
    float var  = sq * (1.f / 256.f) - mean * mean;
    float rstd = rsqrtf(var + 1e-5f);
    __nv_bfloat16* outr = out + (size_t)row * CH;
#pragma unroll
    for (int i = 0; i < 8; i++) {
        int c = lane + 32 * i;
        outr[c] = __float2bfloat16((v[i] - mean) * rstd * g[c] + b[c]);
    }
}

// ---------------- bf16 tensor-core GEMM (R9 config: 128x128, 2 CTA/SM) ------------
#define ALD2 56
#define BLD2 136
#define A_ST2 (128 * ALD2)
#define B_ST2 (32 * BLD2)
#define GSMEM ((3 * (A_ST2 + B_ST2)) * 2)

__global__ void __launch_bounds__(256, 2)
gemm_bf16(const __nv_bfloat16* __restrict__ A, const __nv_bfloat16* __restrict__ B,
          const float* __restrict__ bias, const float* __restrict__ R,
          float* __restrict__ C, __nv_bfloat16* __restrict__ H,
          int M, int N, int K, int epi) {
    extern __shared__ __nv_bfloat16 sm2[];
    __nv_bfloat16* Asm = sm2;
    __nv_bfloat16* Bsm = sm2 + 3 * A_ST2;

    int tid = threadIdx.x, lane = tid & 31, warp = tid >> 5;
    int wr = warp >> 1, wc = warp & 1;
    int row0 = blockIdx.y * 128, col0 = blockIdx.x * 128;
    int gID = lane >> 2, tig = lane & 3;

    float acc[2][8][4] = {};
    int ntile = K / 32;

    int a_off = (wr * 32 + (lane & 15)) * ALD2 + ((lane >> 4) & 1) * 8;
    int b_off = (lane & 15) * BLD2 + wc * 64 + ((lane >> 4) & 1) * 8;
    unsigned smem_base = (unsigned)__cvta_generic_to_shared(sm2);
    unsigned aAddr[3], bAddr[3];
#pragma unroll
    for (int s = 0; s < 3; s++) {
        aAddr[s] = smem_base + (s * A_ST2 + a_off) * 2;
        bAddr[s] = smem_base + ((3 * A_ST2) + s * B_ST2 + b_off) * 2;
    }

#define LOAD_STAGE(st, t)                                                       \
    {                                                                           \
        __nv_bfloat16* as = Asm + (st) * A_ST2;                                 \
        _Pragma("unroll")                                                       \
        for (int i = 0; i < 2; i++) {                                           \
            int id = tid + i * 256;                                             \
            int r = id >> 2, c8 = (id & 3) * 8;                                 \
            cp16(&as[r * ALD2 + c8], A + (size_t)(row0 + r) * K + (t) * 32 + c8); \
        }                                                                       \
        __nv_bfloat16* bs = Bsm + (st) * B_ST2;                                 \
        _Pragma("unroll")                                                       \
        for (int i = 0; i < 2; i++) {                                           \
            int id = tid + i * 256;                                             \
            int r = id >> 4, c = (id & 15) * 8;                                 \
            cp16(&bs[r * BLD2 + c], B + (size_t)((t) * 32 + r) * N + col0 + c); \
        }                                                                       \
    }

    LOAD_STAGE(0, 0);
    asm volatile("cp.async.commit_group;\n");
    LOAD_STAGE(1, 1);
    asm volatile("cp.async.commit_group;\n");

    for (int t = 0; t < ntile; t++) {
        asm volatile("cp.async.wait_group 1;\n");
        __syncthreads();
        if (t + 2 < ntile) LOAD_STAGE((t + 2) % 3, t + 2);
        asm volatile("cp.async.commit_group;\n");

        int s = t % 3;
#pragma unroll
        for (int step = 0; step < 2; step++) {
            unsigned Af[2][4], Bf[4][4];
#pragma unroll
            for (int mt = 0; mt < 2; mt++)
                ldsm_x4(Af[mt], aAddr[s] + (mt * 16 * ALD2 + step * 16) * 2);
#pragma unroll
            for (int nb = 0; nb < 4; nb++)
                ldsm_x4t(Bf[nb], bAddr[s] + (step * 16 * BLD2 + nb * 16) * 2);
#pragma unroll
            for (int nb = 0; nb < 4; nb++) {
#pragma unroll
                for (int mt = 0; mt < 2; mt++) {
                    mma_bf16(acc[mt][2 * nb],     Af[mt][0], Af[mt][1], Af[mt][2], Af[mt][3], Bf[nb][0], Bf[nb][1]);
                    mma_bf16(acc[mt][2 * nb + 1], Af[mt][0], Af[mt][1], Af[mt][2], Af[mt][3], Bf[nb][2], Bf[nb][3]);
                }
            }
        }
    }

#pragma unroll
    for (int mt = 0; mt < 2; mt++) {
#pragma unroll
        for (int nt = 0; nt < 8; nt++) {
            int row = row0 + wr * 32 + mt * 16 + gID;
            int col = col0 + wc * 64 + nt * 8 + tig * 2;
            if (epi == 3 && col >= 856) continue;
            float b0 = bias[col], b1 = bias[col + 1];
            float v0 = acc[mt][nt][0] + b0;
            float v1 = acc[mt][nt][1] + b1;
            float v2 = acc[mt][nt][2] + b0;
            float v3 = acc[mt][nt][3] + b1;
            if (epi == 1) {
                v0 = 0.5f * v0 * (1.f + erff(v0 * 0.70710678118654752440f));
                v1 = 0.5f * v1 * (1.f + erff(v1 * 0.70710678118654752440f));
                v2 = 0.5f * v2 * (1.f + erff(v2 * 0.70710678118654752440f));
                v3 = 0.5f * v3 * (1.f + erff(v3 * 0.70710678118654752440f));
                *(__nv_bfloat162*)(H + (size_t)row * N + col) = __floats2bfloat162_rn(v0, v1);
                *(__nv_bfloat162*)(H + (size_t)(row + 8) * N + col) = __floats2bfloat162_rn(v2, v3);
            } else if (epi == 3 && col < 256) {
                int h  = col >> 5, dh = col & 31;
                int n_ = row / LQ, pix = row - n_ * LQ;
                __nv_bfloat16* d0 = H + ((size_t)(n_ * HEADS + h) * LQ + pix) * DH + dh;
                __nv_bfloat162 lohi  = __floats2bfloat162_rn(v0, v1);
                __nv_bfloat162 lohi2 = __floats2bfloat162_rn(v2, v3);
                *(__nv_bfloat162*)d0 = lohi;
                *(__nv_bfloat162*)(d0 + (size_t)8 * DH) = lohi2;
                __nv_bfloat16* d1 = d0 + (TBL + 32);
                *(__nv_bfloat162*)d1 = lohi;
                *(__nv_bfloat162*)(d1 + (size_t)8 * DH) = lohi2;
            } else {
                if (epi == 2) {
                    const float* r0 = R + (size_t)row * N + col;
                    const float* r1 = R + (size_t)(row + 8) * N + col;
                    v0 += r0[0]; v1 += r0[1]; v2 += r1[0]; v3 += r1[1];
                }
                float* d0 = C + (size_t)row * N + col;
                float* d1 = C + (size_t)(row + 8) * N + col;
                d0[0] = v0; d0[1] = v1; d1[0] = v2; d1[1] = v3;
            }
        }
    }
}

// ---------------- fused softmax + deformable bilinear attention ----------------
// Params duplicated per half-warp: sP[h][half][p] (float4 = {o0,o1,w0,w1}, fp32
// weights). Halves are 400B apart -> disjoint smem banks -> both broadcasts
// coalesce into ONE LDS wavefront. No selects in hot loop.
__global__ void deform_kernel(const __nv_bfloat16* __restrict__ valh,
                              const float* __restrict__ proj,
                              const float* __restrict__ refp,
                              __nv_bfloat16* __restrict__ out) {
    __shared__ float4 sP[HEADS][2][NP];

    int bq   = blockIdx.x;
    int n    = bq / LQ;
    int h    = threadIdx.y;
    int lane = threadIdx.x;

    const float* rowp = proj + (size_t)bq * NQP;
    const float* logr = rowp + LOG_COL + h * NP;

    float lg = (lane < NP) ? logr[lane] : -1e30f;
    float mx = lg;
#pragma unroll
    for (int o = 16; o > 0; o >>= 1) mx = fmaxf(mx, __shfl_xor_sync(0xffffffffu, mx, o));
    float e = (lane < NP) ? expf(lg - mx) : 0.f;
    float sum = e;
#pragma unroll
    for (int o = 16; o > 0; o >>= 1) sum += __shfl_xor_sync(0xffffffffu, sum, o);
    float awn = e / sum;

    if (lane < NP) {
        const float* offr = rowp + OFF_COL + h * (NP * 2);
        float rx = refp[(size_t)bq * 2 + 0];
        float ry = refp[(size_t)bq * 2 + 1];
        float gx = fmaf(rx, 96.f, offr[2 * lane]     - 0.5f);
        float gy = fmaf(ry, 96.f, offr[2 * lane + 1] - 0.5f);
        float x0f = floorf(gx), y0f = floorf(gy);
        float fx = gx - x0f, fy = gy - y0f;
        int x0 = (int)x0f, y0 = (int)y0f;
        int x1 = x0 + 1,   y1 = y0 + 1;
        int px = min(max(x0, 0), 95);
        float wx0 = (x0 >= 0 && x0 < 96) ? (1.f - fx) : 0.f;
        float wx1 = (x1 >= 0 && x1 < 96) ? fx : 0.f;
        bool at0 = (px == x0);
        float wlo = at0 ? wx0 : wx1;     // weight for pixel px      (lanes 0-15)
        float whi = at0 ? wx1 : 0.f;     // weight for pixel px+1    (lanes 16-31)
        float wy0 = (y0 >= 0 && y0 < 96) ? (1.f - fy) : 0.f;
        float wy1 = (y1 >= 0 && y1 < 96) ? fy : 0.f;
        int ry0 = min(max(y0, 0), 95);
        int ry1 = min(max(y1, 0), 95);
        int tb = (px & 1) ? (TBLBYTES + 64) : 0;   // odd px -> 64B-offset copy (aligned)
        int o0 = tb + (ry0 * 96 + px) * (DH * 2);
        int o1 = tb + (ry1 * 96 + px) * (DH * 2);
        float fo0 = __int_as_float(o0), fo1 = __int_as_float(o1);
        sP[h][0][lane] = make_float4(fo0, fo1, wy0 * wlo * awn, wy1 * wlo * awn);
        sP[h][1][lane] = make_float4(fo0, fo1, wy0 * whi * awn, wy1 * whi * awn);
    }
    __syncwarp();

    const char* vb = (const char*)(valh + (size_t)(n * HEADS + h) * LQ * DH) + lane * 4;
    const float4* myP = sP[h][lane >> 4];

    float accx = 0.f, accy = 0.f;
#pragma unroll
    for (int p = 0; p < NP; p++) {
        float4 q = myP[p];
        int   b0 = __float_as_int(q.x);
        int   b1 = __float_as_int(q.y);
        unsigned u0 = *(const unsigned*)(vb + b0);
        unsigned u1 = *(const unsigned*)(vb + b1);
        accx = fmaf(q.z, __uint_as_float(u0 << 16), accx);
        accy = fmaf(q.z, __uint_as_float(u0 & 0xffff0000u), accy);
        accx = fmaf(q.w, __uint_as_float(u1 << 16), accx);
        accy = fmaf(q.w, __uint_as_float(u1 & 0xffff0000u), accy);
    }
    accx += __shfl_xor_sync(0xffffffffu, accx, 16);
    accy += __shfl_xor_sync(0xffffffffu, accy, 16);

    if (lane < 16) {
        *(__nv_bfloat162*)(out + (size_t)bq * CH + h * DH + lane * 2) =
            __floats2bfloat162_rn(accx, accy);
    }
}

// ---------------- launch ----------------
extern "C" void kernel_launch(void* const* d_in, const int* in_sizes, int n_in,
                              void* d_out, int out_size) {
    const float* x      = (const float*)d_in[0];
    const float* refp   = (const float*)d_in[1];
    const float* ln1_g  = (const float*)d_in[4];
    const float* ln1_b  = (const float*)d_in[5];
    const float* w_off  = (const float*)d_in[6];
    const float* b_off  = (const float*)d_in[7];
    const float* w_attn = (const float*)d_in[8];
    const float* b_attn = (const float*)d_in[9];
    const float* w_val  = (const float*)d_in[10];
    const float* b_val  = (const float*)d_in[11];
    const float* w_out  = (const float*)d_in[12];
    const float* b_out  = (const float*)d_in[13];
    const float* ln2_g  = (const float*)d_in[14];
    const float* ln2_b  = (const float*)d_in[15];
    const float* w_fc1  = (const float*)d_in[16];
    const float* b_fc1  = (const float*)d_in[17];
    const float* w_fc2  = (const float*)d_in[18];
    const float* b_fc2  = (const float*)d_in[19];
    float* out = (float*)d_out;

    float *p_proj, *p_x1, *p_bq;
    __nv_bfloat16 *p_qh, *p_valh, *p_attnh, *p_yh, *p_h1h;
    __nv_bfloat16 *p_wqh, *p_wouth, *p_wfc1h, *p_wfc2h;
    cudaGetSymbolAddress((void**)&p_qh,    g_qh);
    cudaGetSymbolAddress((void**)&p_proj,  g_proj);
    cudaGetSymbolAddress((void**)&p_valh,  g_valh);
    cudaGetSymbolAddress((void**)&p_attnh, g_attnh);
    cudaGetSymbolAddress((void**)&p_x1,    g_x1);
    cudaGetSymbolAddress((void**)&p_yh,    g_yh);
    cudaGetSymbolAddress((void**)&p_h1h,   g_h1h);
    cudaGetSymbolAddress((void**)&p_wqh,   g_wqh);
    cudaGetSymbolAddress((void**)&p_bq,    g_bq);
    cudaGetSymbolAddress((void**)&p_wouth, g_wouth);
    cudaGetSymbolAddress((void**)&p_wfc1h, g_wfc1h);
    cudaGetSymbolAddress((void**)&p_wfc2h, g_wfc2h);

    static bool attr_done = false;
    if (!attr_done) {
        cudaFuncSetAttribute(gemm_bf16, cudaFuncAttributeMaxDynamicSharedMemorySize, GSMEM);
        attr_done = true;
    }

    int prep_total = WQ_N + W2_N + W3_N + W4_N;
    prep_all<<<(prep_total + 255) / 256, 256>>>(
        w_val, w_off, w_attn, b_val, b_off, b_attn, w_out, w_fc1, w_fc2,
        p_wqh, p_bq, p_wouth, p_wfc1h, p_wfc2h);

    dim3 lnBlock(32, 8);
    int  lnGrid = M_TOT / 8;

    // 1) LN1 -> bf16 q
    ln_kernel<<<lnGrid, lnBlock>>>(x, ln1_g, ln1_b, p_qh);
    // 2) fused q-projection: value -> dual bf16 tables, off/logit -> fp32
    gemm_bf16<<<dim3(NQP / 128, M_TOT / 128), 256, GSMEM>>>(
        p_qh, p_wqh, p_bq, nullptr, p_proj, p_valh, M_TOT, NQP, CH, 3);
    // 3) deform attention -> bf16
    deform_kernel<<<M_TOT, dim3(32, 8)>>>(p_valh, p_proj, refp, p_attnh);
    // 4) x1 = x + attn @ w_out + b_out (fp32)
    gemm_bf16<<<dim3(CH / 128, M_TOT / 128), 256, GSMEM>>>(
        p_attnh, p_wouth, b_out, x, p_x1, nullptr, M_TOT, CH, CH, 2);
    // 5) LN2 -> bf16 y
    ln_kernel<<<lnGrid, lnBlock>>>(p_x1, ln2_g, ln2_b, p_yh);
    // 6) h1 = gelu(y @ w_fc1 + b_fc1) -> bf16
    gemm_bf16<<<dim3(HID / 128, M_TOT / 128), 256, GSMEM>>>(
        p_yh, p_wfc1h, b_fc1, nullptr, nullptr, p_h1h, M_TOT, HID, CH, 1);
    // 7) out = x1 + h1 @ w_fc2 + b_fc2 (fp32)
    gemm_bf16<<<dim3(CH / 128, M_TOT / 128), 256, GSMEM>>>(
        p_h1h, p_wfc2h, b_fc2, p_x1, out, nullptr, M_TOT, CH, HID, 2);
}

// round 14
// speedup vs baseline: 1.0778x; 1.0359x over previous
#include <cuda_runtime.h>
#include <cuda_bf16.h>
#include <math.h>

#define LQ     9216
#define NBATCH 2
#define M_TOT  (NBATCH * LQ)     // 18432
#define CH     256
#define HEADS  8
#define NP     25
#define DH     32
#define HID    1024
#define NQP    896               // [val 256 | off 400 | logit 200 | pad 40]
#define OFF_COL  256
#define LOG_COL  656

#define TBL      (NBATCH * HEADS * LQ * DH)
#define TBLBYTES (TBL * 2)

#define WQ_N   (CH * NQP)
#define W2_N   (CH * CH)
#define W3_N   (CH * HID)
#define W4_N   (HID * CH)
#define PREP_N (WQ_N + W2_N + W3_N + W4_N)   // 819200
#define LN_BLOCKS   (M_TOT / 8)              // 2304
#define PREP_BLOCKS (PREP_N / 256)           // 3200

// ---------------- scratch ----------------
__device__ __nv_bfloat16 g_qh   [M_TOT * CH];
__device__ float         g_proj [M_TOT * NQP];
__device__ __align__(128) __nv_bfloat16 g_valh[2 * TBL + 96];
__device__ __nv_bfloat16 g_attnh[M_TOT * CH];
__device__ float         g_x1   [M_TOT * CH];
__device__ __nv_bfloat16 g_yh   [M_TOT * CH];
__device__ __nv_bfloat16 g_h1h  [M_TOT * HID];
__device__ __nv_bfloat16 g_wqh  [CH * NQP];
__device__ float         g_bq   [NQP];
__device__ __nv_bfloat16 g_wouth[CH * CH];
__device__ __nv_bfloat16 g_wfc1h[CH * HID];
__device__ __nv_bfloat16 g_wfc2h[HID * CH];

__device__ __forceinline__ void cp16(void* s, const void* g) {
    unsigned sa = (unsigned)__cvta_generic_to_shared(s);
    asm volatile("cp.async.cg.shared.global [%0], [%1], 16;\n" :: "r"(sa), "l"(g));
}

__device__ __forceinline__ void mma_bf16(float c[4], unsigned a0, unsigned a1,
                                         unsigned a2, unsigned a3,
                                         unsigned b0, unsigned b1) {
    asm volatile(
        "mma.sync.aligned.m16n8k16.row.col.f32.bf16.bf16.f32 "
        "{%0,%1,%2,%3},{%4,%5,%6,%7},{%8,%9},{%0,%1,%2,%3};\n"
        : "+f"(c[0]), "+f"(c[1]), "+f"(c[2]), "+f"(c[3])
        : "r"(a0), "r"(a1), "r"(a2), "r"(a3), "r"(b0), "r"(b1));
}

__device__ __forceinline__ void ldsm_x4(unsigned r[4], unsigned addr) {
    asm volatile("ldmatrix.sync.aligned.m8n8.x4.shared.b16 {%0,%1,%2,%3}, [%4];"
                 : "=r"(r[0]), "=r"(r[1]), "=r"(r[2]), "=r"(r[3]) : "r"(addr));
}
__device__ __forceinline__ void ldsm_x4t(unsigned r[4], unsigned addr) {
    asm volatile("ldmatrix.sync.aligned.m8n8.x4.trans.shared.b16 {%0,%1,%2,%3}, [%4];"
                 : "=r"(r[0]), "=r"(r[1]), "=r"(r[2]), "=r"(r[3]) : "r"(addr));
}

// ---------------- merged LN1 + weight-prep kernel ----------------
// blocks [0, LN_BLOCKS): LayerNorm on x -> bf16 q
// blocks [LN_BLOCKS, LN_BLOCKS+PREP_BLOCKS): weight fuse/convert
__global__ void ln1_prep(const float* __restrict__ x, const float* __restrict__ g,
                         const float* __restrict__ b, __nv_bfloat16* __restrict__ q,
                         const float* __restrict__ w_val, const float* __restrict__ w_off,
                         const float* __restrict__ w_attn, const float* __restrict__ b_val,
                         const float* __restrict__ b_off, const float* __restrict__ b_attn,
                         const float* __restrict__ w_out, const float* __restrict__ w_fc1,
                         const float* __restrict__ w_fc2,
                         __nv_bfloat16* __restrict__ wq, float* __restrict__ bq,
                         __nv_bfloat16* __restrict__ d_out, __nv_bfloat16* __restrict__ d_fc1,
                         __nv_bfloat16* __restrict__ d_fc2) {
    if (blockIdx.x < LN_BLOCKS) {
        int lane = threadIdx.x & 31, wy = threadIdx.x >> 5;
        int row  = blockIdx.x * 8 + wy;
        const float* xr = x + (size_t)row * CH;
        float v[8], s = 0.f, sq = 0.f;
#pragma unroll
        for (int i = 0; i < 8; i++) {
            v[i] = xr[lane + 32 * i];
            s += v[i]; sq += v[i] * v[i];
        }
#pragma unroll
        for (int o = 16; o > 0; o >>= 1) {
            s  += __shfl_xor_sync(0xffffffffu, s,  o);
            sq += __shfl_xor_sync(0xffffffffu, sq, o);
        }
        float mean = s * (1.f / 256.f);
        float var  = sq * (1.f / 256.f) - mean * mean;
        float rstd = rsqrtf(var + 1e-5f);
        __nv_bfloat16* outr = q + (size_t)row * CH;
#pragma unroll
        for (int i = 0; i < 8; i++) {
            int c = lane + 32 * i;
            outr[c] = __float2bfloat16((v[i] - mean) * rstd * g[c] + b[c]);
        }
    } else {
        int i = (blockIdx.x - LN_BLOCKS) * 256 + threadIdx.x;
        if (i < WQ_N) {
            int row = i / NQP, col = i - row * NQP;
            float v;
            if      (col < 256) v = w_val [row * 256 + col];
            else if (col < 656) v = w_off [row * 400 + (col - 256)];
            else if (col < 856) v = w_attn[row * 200 + (col - 656)];
            else                v = 0.f;
            wq[i] = __float2bfloat16(v);
            if (row == 0) {
                float bb;
                if      (col < 256) bb = b_val [col];
                else if (col < 656) bb = b_off [col - 256];
                else if (col < 856) bb = b_attn[col - 656];
                else                bb = 0.f;
                bq[col] = bb;
            }
        } else if (i < WQ_N + W2_N) {
            int j = i - WQ_N;
            d_out[j] = __float2bfloat16(w_out[j]);
        } else if (i < WQ_N + W2_N + W3_N) {
            int j = i - WQ_N - W2_N;
            d_fc1[j] = __float2bfloat16(w_fc1[j]);
        } else {
            int j = i - WQ_N - W2_N - W3_N;
            d_fc2[j] = __float2bfloat16(w_fc2[j]);
        }
    }
}

// ---------------- standalone LayerNorm (for LN2), bf16 output ----------------
__global__ void ln_kernel(const float* __restrict__ x, const float* __restrict__ g,
                          const float* __restrict__ b, __nv_bfloat16* __restrict__ out) {
    int row  = blockIdx.x * blockDim.y + threadIdx.y;
    int lane = threadIdx.x;
    const float* xr = x + (size_t)row * CH;
    float v[8], s = 0.f, sq = 0.f;
#pragma unroll
    for (int i = 0; i < 8; i++) {
        v[i] = xr[lane + 32 * i];
        s += v[i]; sq += v[i] * v[i];
    }
#pragma unroll
    for (int o = 16; o > 0; o >>= 1) {
        s  += __shfl_xor_sync(0xffffffffu, s,  o);
        sq += __shfl_xor_sync(0xffffffffu, sq, o);
    }
    float mean = s * (1.f / 256.f);
    float var  = sq * (1.f / 256.f) - mean * mean;
    float rstd = rsqrtf(var + 1e-5f);
    __nv_bfloat16* outr = out + (size_t)row * CH;
#pragma unroll
    for (int i = 0; i < 8; i++) {
        int c = lane + 32 * i;
        outr[c] = __float2bfloat16((v[i] - mean) * rstd * g[c] + b[c]);
    }
}

// ---------------- bf16 tensor-core GEMM: 128x128 tile, K-chunk 64, 2-stage -----
#define ALD3 72     // A smem row stride (bf16): 64 data + 8 pad
#define BLD3 136    // B smem row stride: 128 data + 8 pad
#define A_ST3 (128 * ALD3)
#define B_ST3 (64 * BLD3)
#define GSMEM ((2 * (A_ST3 + B_ST3)) * 2)

__global__ void __launch_bounds__(256, 2)
gemm_bf16(const __nv_bfloat16* __restrict__ A, const __nv_bfloat16* __restrict__ B,
          const float* __restrict__ bias, const float* __restrict__ R,
          float* __restrict__ C, __nv_bfloat16* __restrict__ H,
          int M, int N, int K, int epi) {
    extern __shared__ __nv_bfloat16 sm2[];
    __nv_bfloat16* Asm = sm2;
    __nv_bfloat16* Bsm = sm2 + 2 * A_ST3;

    int tid = threadIdx.x, lane = tid & 31, warp = tid >> 5;
    int wr = warp >> 1, wc = warp & 1;
    int row0 = blockIdx.y * 128, col0 = blockIdx.x * 128;
    int gID = lane >> 2, tig = lane & 3;

    float acc[2][8][4] = {};
    int ntile = K >> 6;      // K-chunks of 64

    int a_off = (wr * 32 + (lane & 15)) * ALD3 + ((lane >> 4) & 1) * 8;
    int b_off = (lane & 15) * BLD3 + wc * 64 + ((lane >> 4) & 1) * 8;
    unsigned smem_base = (unsigned)__cvta_generic_to_shared(sm2);
    unsigned aAddr[2], bAddr[2];
#pragma unroll
    for (int s = 0; s < 2; s++) {
        aAddr[s] = smem_base + (s * A_ST3 + a_off) * 2;
        bAddr[s] = smem_base + ((2 * A_ST3) + s * B_ST3 + b_off) * 2;
    }

#define LOAD_STAGE(st, t)                                                       \
    {                                                                           \
        __nv_bfloat16* as = Asm + (st) * A_ST3;                                 \
        _Pragma("unroll")                                                       \
        for (int i = 0; i < 4; i++) {                                           \
            int id = tid + i * 256;                                             \
            int r = id >> 3, c8 = (id & 7) * 8;                                 \
            cp16(&as[r * ALD3 + c8], A + (size_t)(row0 + r) * K + (t) * 64 + c8); \
        }                                                                       \
        __nv_bfloat16* bs = Bsm + (st) * B_ST3;                                 \
        _Pragma("unroll")                                                       \
        for (int i = 0; i < 4; i++) {                                           \
            int id = tid + i * 256;                                             \
            int r = id >> 4, c = (id & 15) * 8;                                 \
            cp16(&bs[r * BLD3 + c], B + (size_t)((t) * 64 + r) * N + col0 + c); \
        }                                                                       \
    }

    LOAD_STAGE(0, 0);
    asm volatile("cp.async.commit_group;\n");
    if (ntile > 1) {
        LOAD_STAGE(1, 1);
        asm volatile("cp.async.commit_group;\n");
    }

    for (int t = 0; t < ntile; t++) {
        if (t + 1 < ntile) asm volatile("cp.async.wait_group 1;\n");
        else               asm volatile("cp.async.wait_group 0;\n");
        __syncthreads();

        int s = t & 1;
#pragma unroll
        for (int step = 0; step < 4; step++) {
            unsigned Af[2][4], Bf[4][4];
#pragma unroll
            for (int mt = 0; mt < 2; mt++)
                ldsm_x4(Af[mt], aAddr[s] + (mt * 16 * ALD3 + step * 16) * 2);
#pragma unroll
            for (int nb = 0; nb < 4; nb++)
                ldsm_x4t(Bf[nb], bAddr[s] + (step * 16 * BLD3 + nb * 16) * 2);
#pragma unroll
            for (int nb = 0; nb < 4; nb++) {
#pragma unroll
                for (int mt = 0; mt < 2; mt++) {
                    mma_bf16(acc[mt][2 * nb],     Af[mt][0], Af[mt][1], Af[mt][2], Af[mt][3], Bf[nb][0], Bf[nb][1]);
                    mma_bf16(acc[mt][2 * nb + 1], Af[mt][0], Af[mt][1], Af[mt][2], Af[mt][3], Bf[nb][2], Bf[nb][3]);
                }
            }
        }
        __syncthreads();
        if (t + 2 < ntile) {
            LOAD_STAGE(s, t + 2);
            asm volatile("cp.async.commit_group;\n");
        }
    }

#pragma unroll
    for (int mt = 0; mt < 2; mt++) {
#pragma unroll
        for (int nt = 0; nt < 8; nt++) {
            int row = row0 + wr * 32 + mt * 16 + gID;
            int col = col0 + wc * 64 + nt * 8 + tig * 2;
            if (epi == 3 && col >= 856) continue;
            float b0 = bias[col], b1 = bias[col + 1];
            float v0 = acc[mt][nt][0] + b0;
            float v1 = acc[mt][nt][1] + b1;
            float v2 = acc[mt][nt][2] + b0;
            float v3 = acc[mt][nt][3] + b1;
            if (epi == 1) {
                v0 = 0.5f * v0 * (1.f + erff(v0 * 0.70710678118654752440f));
                v1 = 0.5f * v1 * (1.f + erff(v1 * 0.70710678118654752440f));
                v2 = 0.5f * v2 * (1.f + erff(v2 * 0.70710678118654752440f));
                v3 = 0.5f * v3 * (1.f + erff(v3 * 0.70710678118654752440f));
                *(__nv_bfloat162*)(H + (size_t)row * N + col) = __floats2bfloat162_rn(v0, v1);
                *(__nv_bfloat162*)(H + (size_t)(row + 8) * N + col) = __floats2bfloat162_rn(v2, v3);
            } else if (epi == 3 && col < 256) {
                int h  = col >> 5, dh = col & 31;
                int n_ = row / LQ, pix = row - n_ * LQ;
                __nv_bfloat16* d0 = H + ((size_t)(n_ * HEADS + h) * LQ + pix) * DH + dh;
                __nv_bfloat162 lohi  = __floats2bfloat162_rn(v0, v1);
                __nv_bfloat162 lohi2 = __floats2bfloat162_rn(v2, v3);
                *(__nv_bfloat162*)d0 = lohi;
                *(__nv_bfloat162*)(d0 + (size_t)8 * DH) = lohi2;
                __nv_bfloat16* d1 = d0 + (TBL + 32);
                *(__nv_bfloat162*)d1 = lohi;
                *(__nv_bfloat162*)(d1 + (size_t)8 * DH) = lohi2;
            } else {
                if (epi == 2) {
                    const float* r0 = R + (size_t)row * N + col;
                    const float* r1 = R + (size_t)(row + 8) * N + col;
                    v0 += r0[0]; v1 += r0[1]; v2 += r1[0]; v3 += r1[1];
                }
                float* d0 = C + (size_t)row * N + col;
                float* d1 = C + (size_t)(row + 8) * N + col;
                d0[0] = v0; d0[1] = v1; d1[0] = v2; d1[1] = v3;
            }
        }
    }
}

// ---------------- fused softmax + deformable bilinear attention (R13) ----------
__global__ void deform_kernel(const __nv_bfloat16* __restrict__ valh,
                              const float* __restrict__ proj,
                              const float* __restrict__ refp,
                              __nv_bfloat16* __restrict__ out) {
    __shared__ float4 sP[HEADS][2][NP];

    int bq   = blockIdx.x;
    int n    = bq / LQ;
    int h    = threadIdx.y;
    int lane = threadIdx.x;

    const float* rowp = proj + (size_t)bq * NQP;
    const float* logr = rowp + LOG_COL + h * NP;

    float lg = (lane < NP) ? logr[lane] : -1e30f;
    float mx = lg;
#pragma unroll
    for (int o = 16; o > 0; o >>= 1) mx = fmaxf(mx, __shfl_xor_sync(0xffffffffu, mx, o));
    float e = (lane < NP) ? expf(lg - mx) : 0.f;
    float sum = e;
#pragma unroll
    for (int o = 16; o > 0; o >>= 1) sum += __shfl_xor_sync(0xffffffffu, sum, o);
    float awn = e / sum;

    if (lane < NP) {
        const float* offr = rowp + OFF_COL + h * (NP * 2);
        float rx = refp[(size_t)bq * 2 + 0];
        float ry = refp[(size_t)bq * 2 + 1];
        float gx = fmaf(rx, 96.f, offr[2 * lane]     - 0.5f);
        float gy = fmaf(ry, 96.f, offr[2 * lane + 1] - 0.5f);
        float x0f = floorf(gx), y0f = floorf(gy);
        float fx = gx - x0f, fy = gy - y0f;
        int x0 = (int)x0f, y0 = (int)y0f;
        int x1 = x0 + 1,   y1 = y0 + 1;
        int px = min(max(x0, 0), 95);
        float wx0 = (x0 >= 0 && x0 < 96) ? (1.f - fx) : 0.f;
        float wx1 = (x1 >= 0 && x1 < 96) ? fx : 0.f;
        bool at0 = (px == x0);
        float wlo = at0 ? wx0 : wx1;
        float whi = at0 ? wx1 : 0.f;
        float wy0 = (y0 >= 0 && y0 < 96) ? (1.f - fy) : 0.f;
        float wy1 = (y1 >= 0 && y1 < 96) ? fy : 0.f;
        int ry0 = min(max(y0, 0), 95);
        int ry1 = min(max(y1, 0), 95);
        int tb = (px & 1) ? (TBLBYTES + 64) : 0;
        int o0 = tb + (ry0 * 96 + px) * (DH * 2);
        int o1 = tb + (ry1 * 96 + px) * (DH * 2);
        float fo0 = __int_as_float(o0), fo1 = __int_as_float(o1);
        sP[h][0][lane] = make_float4(fo0, fo1, wy0 * wlo * awn, wy1 * wlo * awn);
        sP[h][1][lane] = make_float4(fo0, fo1, wy0 * whi * awn, wy1 * whi * awn);
    }
    __syncwarp();

    const char* vb = (const char*)(valh + (size_t)(n * HEADS + h) * LQ * DH) + lane * 4;
    const float4* myP = sP[h][lane >> 4];

    float accx = 0.f, accy = 0.f;
#pragma unroll
    for (int p = 0; p < NP; p++) {
        float4 q = myP[p];
        int   b0 = __float_as_int(q.x);
        int   b1 = __float_as_int(q.y);
        unsigned u0 = *(const unsigned*)(vb + b0);
        unsigned u1 = *(const unsigned*)(vb + b1);
        accx = fmaf(q.z, __uint_as_float(u0 << 16), accx);
        accy = fmaf(q.z, __uint_as_float(u0 & 0xffff0000u), accy);
        accx = fmaf(q.w, __uint_as_float(u1 << 16), accx);
        accy = fmaf(q.w, __uint_as_float(u1 & 0xffff0000u), accy);
    }
    accx += __shfl_xor_sync(0xffffffffu, accx, 16);
    accy += __shfl_xor_sync(0xffffffffu, accy, 16);

    if (lane < 16) {
        *(__nv_bfloat162*)(out + (size_t)bq * CH + h * DH + lane * 2) =
            __floats2bfloat162_rn(accx, accy);
    }
}

// ---------------- launch ----------------
extern "C" void kernel_launch(void* const* d_in, const int* in_sizes, int n_in,
                              void* d_out, int out_size) {
    const float* x      = (const float*)d_in[0];
    const float* refp   = (const float*)d_in[1];
    const float* ln1_g  = (const float*)d_in[4];
    const float* ln1_b  = (const float*)d_in[5];
    const float* w_off  = (const float*)d_in[6];
    const float* b_off  = (const float*)d_in[7];
    const float* w_attn = (const float*)d_in[8];
    const float* b_attn = (const float*)d_in[9];
    const float* w_val  = (const float*)d_in[10];
    const float* b_val  = (const float*)d_in[11];
    const float* w_out  = (const float*)d_in[12];
    const float* b_out  = (const float*)d_in[13];
    const float* ln2_g  = (const float*)d_in[14];
    const float* ln2_b  = (const float*)d_in[15];
    const float* w_fc1  = (const float*)d_in[16];
    const float* b_fc1  = (const float*)d_in[17];
    const float* w_fc2  = (const float*)d_in[18];
    const float* b_fc2  = (const float*)d_in[19];
    float* out = (float*)d_out;

    float *p_proj, *p_x1, *p_bq;
    __nv_bfloat16 *p_qh, *p_valh, *p_attnh, *p_yh, *p_h1h;
    __nv_bfloat16 *p_wqh, *p_wouth, *p_wfc1h, *p_wfc2h;
    cudaGetSymbolAddress((void**)&p_qh,    g_qh);
    cudaGetSymbolAddress((void**)&p_proj,  g_proj);
    cudaGetSymbolAddress((void**)&p_valh,  g_valh);
    cudaGetSymbolAddress((void**)&p_attnh, g_attnh);
    cudaGetSymbolAddress((void**)&p_x1,    g_x1);
    cudaGetSymbolAddress((void**)&p_yh,    g_yh);
    cudaGetSymbolAddress((void**)&p_h1h,   g_h1h);
    cudaGetSymbolAddress((void**)&p_wqh,   g_wqh);
    cudaGetSymbolAddress((void**)&p_bq,    g_bq);
    cudaGetSymbolAddress((void**)&p_wouth, g_wouth);
    cudaGetSymbolAddress((void**)&p_wfc1h, g_wfc1h);
    cudaGetSymbolAddress((void**)&p_wfc2h, g_wfc2h);

    static bool attr_done = false;
    if (!attr_done) {
        cudaFuncSetAttribute(gemm_bf16, cudaFuncAttributeMaxDynamicSharedMemorySize, GSMEM);
        attr_done = true;
    }

    // 1) LN1 + weight prep (merged, independent blocks)
    ln1_prep<<<LN_BLOCKS + PREP_BLOCKS, 256>>>(
        x, ln1_g, ln1_b, p_qh,
        w_val, w_off, w_attn, b_val, b_off, b_attn, w_out, w_fc1, w_fc2,
        p_wqh, p_bq, p_wouth, p_wfc1h, p_wfc2h);

    // 2) fused q-projection: value -> dual bf16 tables, off/logit -> fp32
    gemm_bf16<<<dim3(NQP / 128, M_TOT / 128), 256, GSMEM>>>(
        p_qh, p_wqh, p_bq, nullptr, p_proj, p_valh, M_TOT, NQP, CH, 3);
    // 3) deform attention -> bf16
    deform_kernel<<<M_TOT, dim3(32, 8)>>>(p_valh, p_proj, refp, p_attnh);
    // 4) x1 = x + attn @ w_out + b_out (fp32)
    gemm_bf16<<<dim3(CH / 128, M_TOT / 128), 256, GSMEM>>>(
        p_attnh, p_wouth, b_out, x, p_x1, nullptr, M_TOT, CH, CH, 2);
    // 5) LN2 -> bf16 y
    ln_kernel<<<M_TOT / 8, dim3(32, 8)>>>(p_x1, ln2_g, ln2_b, p_yh);
    // 6) h1 = gelu(y @ w_fc1 + b_fc1) -> bf16
    gemm_bf16<<<dim3(HID / 128, M_TOT / 128), 256, GSMEM>>>(
        p_yh, p_wfc1h, b_fc1, nullptr, nullptr, p_h1h, M_TOT, HID, CH, 1);
    // 7) out = x1 + h1 @ w_fc2 + b_fc2 (fp32)
    gemm_bf16<<<dim3(CH / 128, M_TOT / 128), 256, GSMEM>>>(
        p_h1h, p_wfc2h, b_fc2, p_x1, out, nullptr, M_TOT, CH, HID, 2);
}

// round 15
// speedup vs baseline: 1.0864x; 1.0080x over previous
#include <cuda_runtime.h>
#include <cuda_bf16.h>
#include <math.h>

#define LQ     9216
#define NBATCH 2
#define M_TOT  (NBATCH * LQ)     // 18432
#define CH     256
#define HEADS  8
#define NP     25
#define DH     32
#define HID    1024
#define NQP    896               // [val 256 | off 400 | logit 200 | pad 40]
#define OFF_COL  256
#define LOG_COL  656

#define TBL      (NBATCH * HEADS * LQ * DH)
#define TBLBYTES (TBL * 2)

#define WQ_N   (CH * NQP)
#define W2_N   (CH * CH)
#define W3_N   (CH * HID)
#define W4_N   (HID * CH)
#define PREP_N (WQ_N + W2_N + W3_N + W4_N)   // 819200
#define LN_BLOCKS   (M_TOT / 8)              // 2304
#define PREP_BLOCKS (PREP_N / 256)           // 3200

// ---------------- scratch ----------------
__device__ __nv_bfloat16 g_qh   [M_TOT * CH];
__device__ float         g_proj [M_TOT * NQP];
__device__ __align__(128) __nv_bfloat16 g_valh[2 * TBL + 96];
__device__ __nv_bfloat16 g_attnh[M_TOT * CH];
__device__ float         g_x1   [M_TOT * CH];
__device__ __nv_bfloat16 g_yh   [M_TOT * CH];
__device__ __nv_bfloat16 g_h1h  [M_TOT * HID];
__device__ __nv_bfloat16 g_wqh  [CH * NQP];
__device__ float         g_bq   [NQP];
__device__ __nv_bfloat16 g_wouth[CH * CH];
__device__ __nv_bfloat16 g_wfc1h[CH * HID];
__device__ __nv_bfloat16 g_wfc2h[HID * CH];

__device__ __forceinline__ void cp16(void* s, const void* g) {
    unsigned sa = (unsigned)__cvta_generic_to_shared(s);
    asm volatile("cp.async.cg.shared.global [%0], [%1], 16;\n" :: "r"(sa), "l"(g));
}

__device__ __forceinline__ void mma_bf16(float c[4], unsigned a0, unsigned a1,
                                         unsigned a2, unsigned a3,
                                         unsigned b0, unsigned b1) {
    asm volatile(
        "mma.sync.aligned.m16n8k16.row.col.f32.bf16.bf16.f32 "
        "{%0,%1,%2,%3},{%4,%5,%6,%7},{%8,%9},{%0,%1,%2,%3};\n"
        : "+f"(c[0]), "+f"(c[1]), "+f"(c[2]), "+f"(c[3])
        : "r"(a0), "r"(a1), "r"(a2), "r"(a3), "r"(b0), "r"(b1));
}

__device__ __forceinline__ void ldsm_x4(unsigned r[4], unsigned addr) {
    asm volatile("ldmatrix.sync.aligned.m8n8.x4.shared.b16 {%0,%1,%2,%3}, [%4];"
                 : "=r"(r[0]), "=r"(r[1]), "=r"(r[2]), "=r"(r[3]) : "r"(addr));
}
__device__ __forceinline__ void ldsm_x4t(unsigned r[4], unsigned addr) {
    asm volatile("ldmatrix.sync.aligned.m8n8.x4.trans.shared.b16 {%0,%1,%2,%3}, [%4];"
                 : "=r"(r[0]), "=r"(r[1]), "=r"(r[2]), "=r"(r[3]) : "r"(addr));
}

// packed f32x2 FMA: acc = v * w + acc  (FFMA2 — PTX-only pattern)
__device__ __forceinline__ void ffma2(unsigned long long& acc, unsigned long long v,
                                      unsigned long long w) {
    asm("fma.rn.f32x2 %0, %1, %2, %0;" : "+l"(acc) : "l"(v), "l"(w));
}

// ---------------- merged LN1 + weight-prep kernel ----------------
__global__ void ln1_prep(const float* __restrict__ x, const float* __restrict__ g,
                         const float* __restrict__ b, __nv_bfloat16* __restrict__ q,
                         const float* __restrict__ w_val, const float* __restrict__ w_off,
                         const float* __restrict__ w_attn, const float* __restrict__ b_val,
                         const float* __restrict__ b_off, const float* __restrict__ b_attn,
                         const float* __restrict__ w_out, const float* __restrict__ w_fc1,
                         const float* __restrict__ w_fc2,
                         __nv_bfloat16* __restrict__ wq, float* __restrict__ bq,
                         __nv_bfloat16* __restrict__ d_out, __nv_bfloat16* __restrict__ d_fc1,
                         __nv_bfloat16* __restrict__ d_fc2) {
    if (blockIdx.x < LN_BLOCKS) {
        int lane = threadIdx.x & 31, wy = threadIdx.x >> 5;
        int row  = blockIdx.x * 8 + wy;
        const float* xr = x + (size_t)row * CH;
        float v[8], s = 0.f, sq = 0.f;
#pragma unroll
        for (int i = 0; i < 8; i++) {
            v[i] = xr[lane + 32 * i];
            s += v[i]; sq += v[i] * v[i];
        }
#pragma unroll
        for (int o = 16; o > 0; o >>= 1) {
            s  += __shfl_xor_sync(0xffffffffu, s,  o);
            sq += __shfl_xor_sync(0xffffffffu, sq, o);
        }
        float mean = s * (1.f / 256.f);
        float var  = sq * (1.f / 256.f) - mean * mean;
        float rstd = rsqrtf(var + 1e-5f);
        __nv_bfloat16* outr = q + (size_t)row * CH;
#pragma unroll
        for (int i = 0; i < 8; i++) {
            int c = lane + 32 * i;
            outr[c] = __float2bfloat16((v[i] - mean) * rstd * g[c] + b[c]);
        }
    } else {
        int i = (blockIdx.x - LN_BLOCKS) * 256 + threadIdx.x;
        if (i < WQ_N) {
            int row = i / NQP, col = i - row * NQP;
            float v;
            if      (col < 256) v = w_val [row * 256 + col];
            else if (col < 656) v = w_off [row * 400 + (col - 256)];
            else if (col < 856) v = w_attn[row * 200 + (col - 656)];
            else                v = 0.f;
            wq[i] = __float2bfloat16(v);
            if (row == 0) {
                float bb;
                if      (col < 256) bb = b_val [col];
                else if (col < 656) bb = b_off [col - 256];
                else if (col < 856) bb = b_attn[col - 656];
                else                bb = 0.f;
                bq[col] = bb;
            }
        } else if (i < WQ_N + W2_N) {
            int j = i - WQ_N;
            d_out[j] = __float2bfloat16(w_out[j]);
        } else if (i < WQ_N + W2_N + W3_N) {
            int j = i - WQ_N - W2_N;
            d_fc1[j] = __float2bfloat16(w_fc1[j]);
        } else {
            int j = i - WQ_N - W2_N - W3_N;
            d_fc2[j] = __float2bfloat16(w_fc2[j]);
        }
    }
}

// ---------------- standalone LayerNorm (for LN2), bf16 output ----------------
__global__ void ln_kernel(const float* __restrict__ x, const float* __restrict__ g,
                          const float* __restrict__ b, __nv_bfloat16* __restrict__ out) {
    int row  = blockIdx.x * blockDim.y + threadIdx.y;
    int lane = threadIdx.x;
    const float* xr = x + (size_t)row * CH;
    float v[8], s = 0.f, sq = 0.f;
#pragma unroll
    for (int i = 0; i < 8; i++) {
        v[i] = xr[lane + 32 * i];
        s += v[i]; sq += v[i] * v[i];
    }
#pragma unroll
    for (int o = 16; o > 0; o >>= 1) {
        s  += __shfl_xor_sync(0xffffffffu, s,  o);
        sq += __shfl_xor_sync(0xffffffffu, sq, o);
    }
    float mean = s * (1.f / 256.f);
    float var  = sq * (1.f / 256.f) - mean * mean;
    float rstd = rsqrtf(var + 1e-5f);
    __nv_bfloat16* outr = out + (size_t)row * CH;
#pragma unroll
    for (int i = 0; i < 8; i++) {
        int c = lane + 32 * i;
        outr[c] = __float2bfloat16((v[i] - mean) * rstd * g[c] + b[c]);
    }
}

// ---------------- bf16 tensor-core GEMM (R14: 128x128 tile, K-chunk 64, 2-stage) ---
#define ALD3 72
#define BLD3 136
#define A_ST3 (128 * ALD3)
#define B_ST3 (64 * BLD3)
#define GSMEM ((2 * (A_ST3 + B_ST3)) * 2)

__global__ void __launch_bounds__(256, 2)
gemm_bf16(const __nv_bfloat16* __restrict__ A, const __nv_bfloat16* __restrict__ B,
          const float* __restrict__ bias, const float* __restrict__ R,
          float* __restrict__ C, __nv_bfloat16* __restrict__ H,
          int M, int N, int K, int epi) {
    extern __shared__ __nv_bfloat16 sm2[];
    __nv_bfloat16* Asm = sm2;
    __nv_bfloat16* Bsm = sm2 + 2 * A_ST3;

    int tid = threadIdx.x, lane = tid & 31, warp = tid >> 5;
    int wr = warp >> 1, wc = warp & 1;
    int row0 = blockIdx.y * 128, col0 = blockIdx.x * 128;
    int gID = lane >> 2, tig = lane & 3;

    float acc[2][8][4] = {};
    int ntile = K >> 6;

    int a_off = (wr * 32 + (lane & 15)) * ALD3 + ((lane >> 4) & 1) * 8;
    int b_off = (lane & 15) * BLD3 + wc * 64 + ((lane >> 4) & 1) * 8;
    unsigned smem_base = (unsigned)__cvta_generic_to_shared(sm2);
    unsigned aAddr[2], bAddr[2];
#pragma unroll
    for (int s = 0; s < 2; s++) {
        aAddr[s] = smem_base + (s * A_ST3 + a_off) * 2;
        bAddr[s] = smem_base + ((2 * A_ST3) + s * B_ST3 + b_off) * 2;
    }

#define LOAD_STAGE(st, t)                                                       \
    {                                                                           \
        __nv_bfloat16* as = Asm + (st) * A_ST3;                                 \
        _Pragma("unroll")                                                       \
        for (int i = 0; i < 4; i++) {                                           \
            int id = tid + i * 256;                                             \
            int r = id >> 3, c8 = (id & 7) * 8;                                 \
            cp16(&as[r * ALD3 + c8], A + (size_t)(row0 + r) * K + (t) * 64 + c8); \
        }                                                                       \
        __nv_bfloat16* bs = Bsm + (st) * B_ST3;                                 \
        _Pragma("unroll")                                                       \
        for (int i = 0; i < 4; i++) {                                           \
            int id = tid + i * 256;                                             \
            int r = id >> 4, c = (id & 15) * 8;                                 \
            cp16(&bs[r * BLD3 + c], B + (size_t)((t) * 64 + r) * N + col0 + c); \
        }                                                                       \
    }

    LOAD_STAGE(0, 0);
    asm volatile("cp.async.commit_group;\n");
    if (ntile > 1) {
        LOAD_STAGE(1, 1);
        asm volatile("cp.async.commit_group;\n");
    }

    for (int t = 0; t < ntile; t++) {
        if (t + 1 < ntile) asm volatile("cp.async.wait_group 1;\n");
        else               asm volatile("cp.async.wait_group 0;\n");
        __syncthreads();

        int s = t & 1;
#pragma unroll
        for (int step = 0; step < 4; step++) {
            unsigned Af[2][4], Bf[4][4];
#pragma unroll
            for (int mt = 0; mt < 2; mt++)
                ldsm_x4(Af[mt], aAddr[s] + (mt * 16 * ALD3 + step * 16) * 2);
#pragma unroll
            for (int nb = 0; nb < 4; nb++)
                ldsm_x4t(Bf[nb], bAddr[s] + (step * 16 * BLD3 + nb * 16) * 2);
#pragma unroll
            for (int nb = 0; nb < 4; nb++) {
#pragma unroll
                for (int mt = 0; mt < 2; mt++) {
                    mma_bf16(acc[mt][2 * nb],     Af[mt][0], Af[mt][1], Af[mt][2], Af[mt][3], Bf[nb][0], Bf[nb][1]);
                    mma_bf16(acc[mt][2 * nb + 1], Af[mt][0], Af[mt][1], Af[mt][2], Af[mt][3], Bf[nb][2], Bf[nb][3]);
                }
            }
        }
        __syncthreads();
        if (t + 2 < ntile) {
            LOAD_STAGE(s, t + 2);
            asm volatile("cp.async.commit_group;\n");
        }
    }

#pragma unroll
    for (int mt = 0; mt < 2; mt++) {
#pragma unroll
        for (int nt = 0; nt < 8; nt++) {
            int row = row0 + wr * 32 + mt * 16 + gID;
            int col = col0 + wc * 64 + nt * 8 + tig * 2;
            if (epi == 3 && col >= 856) continue;
            float b0 = bias[col], b1 = bias[col + 1];
            float v0 = acc[mt][nt][0] + b0;
            float v1 = acc[mt][nt][1] + b1;
            float v2 = acc[mt][nt][2] + b0;
            float v3 = acc[mt][nt][3] + b1;
            if (epi == 1) {
                v0 = 0.5f * v0 * (1.f + erff(v0 * 0.70710678118654752440f));
                v1 = 0.5f * v1 * (1.f + erff(v1 * 0.70710678118654752440f));
                v2 = 0.5f * v2 * (1.f + erff(v2 * 0.70710678118654752440f));
                v3 = 0.5f * v3 * (1.f + erff(v3 * 0.70710678118654752440f));
                *(__nv_bfloat162*)(H + (size_t)row * N + col) = __floats2bfloat162_rn(v0, v1);
                *(__nv_bfloat162*)(H + (size_t)(row + 8) * N + col) = __floats2bfloat162_rn(v2, v3);
            } else if (epi == 3 && col < 256) {
                int h  = col >> 5, dh = col & 31;
                int n_ = row / LQ, pix = row - n_ * LQ;
                __nv_bfloat16* d0 = H + ((size_t)(n_ * HEADS + h) * LQ + pix) * DH + dh;
                __nv_bfloat162 lohi  = __floats2bfloat162_rn(v0, v1);
                __nv_bfloat162 lohi2 = __floats2bfloat162_rn(v2, v3);
                *(__nv_bfloat162*)d0 = lohi;
                *(__nv_bfloat162*)(d0 + (size_t)8 * DH) = lohi2;
                __nv_bfloat16* d1 = d0 + (TBL + 32);
                *(__nv_bfloat162*)d1 = lohi;
                *(__nv_bfloat162*)(d1 + (size_t)8 * DH) = lohi2;
            } else {
                if (epi == 2) {
                    const float* r0 = R + (size_t)row * N + col;
                    const float* r1 = R + (size_t)(row + 8) * N + col;
                    v0 += r0[0]; v1 += r0[1]; v2 += r1[0]; v3 += r1[1];
                }
                float* d0 = C + (size_t)row * N + col;
                float* d1 = C + (size_t)(row + 8) * N + col;
                d0[0] = v0; d0[1] = v1; d1[0] = v2; d1[1] = v3;
            }
        }
    }
}

// ---------------- fused softmax + deformable bilinear attention ----------------
// R13 layout + packed f32x2 FMA hot loop (2 FFMA2 instead of 4 FFMA per pair).
__global__ void deform_kernel(const __nv_bfloat16* __restrict__ valh,
                              const float* __restrict__ proj,
                              const float* __restrict__ refp,
                              __nv_bfloat16* __restrict__ out) {
    __shared__ float4 sP[HEADS][2][NP];

    int bq   = blockIdx.x;
    int n    = bq / LQ;
    int h    = threadIdx.y;
    int lane = threadIdx.x;

    const float* rowp = proj + (size_t)bq * NQP;
    const float* logr = rowp + LOG_COL + h * NP;

    float lg = (lane < NP) ? logr[lane] : -1e30f;
    float mx = lg;
#pragma unroll
    for (int o = 16; o > 0; o >>= 1) mx = fmaxf(mx, __shfl_xor_sync(0xffffffffu, mx, o));
    float e = (lane < NP) ? expf(lg - mx) : 0.f;
    float sum = e;
#pragma unroll
    for (int o = 16; o > 0; o >>= 1) sum += __shfl_xor_sync(0xffffffffu, sum, o);
    float awn = e / sum;

    if (lane < NP) {
        const float* offr = rowp + OFF_COL + h * (NP * 2);
        float rx = refp[(size_t)bq * 2 + 0];
        float ry = refp[(size_t)bq * 2 + 1];
        float gx = fmaf(rx, 96.f, offr[2 * lane]     - 0.5f);
        float gy = fmaf(ry, 96.f, offr[2 * lane + 1] - 0.5f);
        float x0f = floorf(gx), y0f = floorf(gy);
        float fx = gx - x0f, fy = gy - y0f;
        int x0 = (int)x0f, y0 = (int)y0f;
        int x1 = x0 + 1,   y1 = y0 + 1;
        int px = min(max(x0, 0), 95);
        float wx0 = (x0 >= 0 && x0 < 96) ? (1.f - fx) : 0.f;
        float wx1 = (x1 >= 0 && x1 < 96) ? fx : 0.f;
        bool at0 = (px == x0);
        float wlo = at0 ? wx0 : wx1;
        float whi = at0 ? wx1 : 0.f;
        float wy0 = (y0 >= 0 && y0 < 96) ? (1.f - fy) : 0.f;
        float wy1 = (y1 >= 0 && y1 < 96) ? fy : 0.f;
        int ry0 = min(max(y0, 0), 95);
        int ry1 = min(max(y1, 0), 95);
        int tb = (px & 1) ? (TBLBYTES + 64) : 0;
        int o0 = tb + (ry0 * 96 + px) * (DH * 2);
        int o1 = tb + (ry1 * 96 + px) * (DH * 2);
        float fo0 = __int_as_float(o0), fo1 = __int_as_float(o1);
        sP[h][0][lane] = make_float4(fo0, fo1, wy0 * wlo * awn, wy1 * wlo * awn);
        sP[h][1][lane] = make_float4(fo0, fo1, wy0 * whi * awn, wy1 * whi * awn);
    }
    __syncwarp();

    const char* vb = (const char*)(valh + (size_t)(n * HEADS + h) * LQ * DH) + lane * 4;
    const float4* myP = sP[h][lane >> 4];

    unsigned long long acc = 0ull;   // packed {accx, accy}
#pragma unroll
    for (int p = 0; p < NP; p++) {
        float4 q = myP[p];
        int b0 = __float_as_int(q.x);
        int b1 = __float_as_int(q.y);
        unsigned u0 = *(const unsigned*)(vb + b0);
        unsigned u1 = *(const unsigned*)(vb + b1);
        unsigned long long v0, v1, w0, w1;
        {
            unsigned lo0 = u0 << 16, hi0 = u0 & 0xffff0000u;
            unsigned lo1 = u1 << 16, hi1 = u1 & 0xffff0000u;
            asm("mov.b64 %0, {%1,%2};" : "=l"(v0) : "r"(lo0), "r"(hi0));
            asm("mov.b64 %0, {%1,%2};" : "=l"(v1) : "r"(lo1), "r"(hi1));
            unsigned wz = __float_as_uint(q.z), ww = __float_as_uint(q.w);
            asm("mov.b64 %0, {%1,%1};" : "=l"(w0) : "r"(wz));
            asm("mov.b64 %0, {%1,%1};" : "=l"(w1) : "r"(ww));
        }
        ffma2(acc, v0, w0);
        ffma2(acc, v1, w1);
    }
    unsigned alo, ahi;
    asm("mov.b64 {%0,%1}, %2;" : "=r"(alo), "=r"(ahi) : "l"(acc));
    float accx = __uint_as_float(alo);
    float accy = __uint_as_float(ahi);
    accx += __shfl_xor_sync(0xffffffffu, accx, 16);
    accy += __shfl_xor_sync(0xffffffffu, accy, 16);

    if (lane < 16) {
        *(__nv_bfloat162*)(out + (size_t)bq * CH + h * DH + lane * 2) =
            __floats2bfloat162_rn(accx, accy);
    }
}

// ---------------- launch ----------------
extern "C" void kernel_launch(void* const* d_in, const int* in_sizes, int n_in,
                              void* d_out, int out_size) {
    const float* x      = (const float*)d_in[0];
    const float* refp   = (const float*)d_in[1];
    const float* ln1_g  = (const float*)d_in[4];
    const float* ln1_b  = (const float*)d_in[5];
    const float* w_off  = (const float*)d_in[6];
    const float* b_off  = (const float*)d_in[7];
    const float* w_attn = (const float*)d_in[8];
    const float* b_attn = (const float*)d_in[9];
    const float* w_val  = (const float*)d_in[10];
    const float* b_val  = (const float*)d_in[11];
    const float* w_out  = (const float*)d_in[12];
    const float* b_out  = (const float*)d_in[13];
    const float* ln2_g  = (const float*)d_in[14];
    const float* ln2_b  = (const float*)d_in[15];
    const float* w_fc1  = (const float*)d_in[16];
    const float* b_fc1  = (const float*)d_in[17];
    const float* w_fc2  = (const float*)d_in[18];
    const float* b_fc2  = (const float*)d_in[19];
    float* out = (float*)d_out;

    float *p_proj, *p_x1, *p_bq;
    __nv_bfloat16 *p_qh, *p_valh, *p_attnh, *p_yh, *p_h1h;
    __nv_bfloat16 *p_wqh, *p_wouth, *p_wfc1h, *p_wfc2h;
    cudaGetSymbolAddress((void**)&p_qh,    g_qh);
    cudaGetSymbolAddress((void**)&p_proj,  g_proj);
    cudaGetSymbolAddress((void**)&p_valh,  g_valh);
    cudaGetSymbolAddress((void**)&p_attnh, g_attnh);
    cudaGetSymbolAddress((void**)&p_x1,    g_x1);
    cudaGetSymbolAddress((void**)&p_yh,    g_yh);
    cudaGetSymbolAddress((void**)&p_h1h,   g_h1h);
    cudaGetSymbolAddress((void**)&p_wqh,   g_wqh);
    cudaGetSymbolAddress((void**)&p_bq,    g_bq);
    cudaGetSymbolAddress((void**)&p_wouth, g_wouth);
    cudaGetSymbolAddress((void**)&p_wfc1h, g_wfc1h);
    cudaGetSymbolAddress((void**)&p_wfc2h, g_wfc2h);

    static bool attr_done = false;
    if (!attr_done) {
        cudaFuncSetAttribute(gemm_bf16, cudaFuncAttributeMaxDynamicSharedMemorySize, GSMEM);
        attr_done = true;
    }

    // 1) LN1 + weight prep (merged)
    ln1_prep<<<LN_BLOCKS + PREP_BLOCKS, 256>>>(
        x, ln1_g, ln1_b, p_qh,
        w_val, w_off, w_attn, b_val, b_off, b_attn, w_out, w_fc1, w_fc2,
        p_wqh, p_bq, p_wouth, p_wfc1h, p_wfc2h);

    // 2) fused q-projection: value -> dual bf16 tables, off/logit -> fp32
    gemm_bf16<<<dim3(NQP / 128, M_TOT / 128), 256, GSMEM>>>(
        p_qh, p_wqh, p_bq, nullptr, p_proj, p_valh, M_TOT, NQP, CH, 3);
    // 3) deform attention -> bf16
    deform_kernel<<<M_TOT, dim3(32, 8)>>>(p_valh, p_proj, refp, p_attnh);
    // 4) x1 = x + attn @ w_out + b_out (fp32)
    gemm_bf16<<<dim3(CH / 128, M_TOT / 128), 256, GSMEM>>>(
        p_attnh, p_wouth, b_out, x, p_x1, nullptr, M_TOT, CH, CH, 2);
    // 5) LN2 -> bf16 y
    ln_kernel<<<M_TOT / 8, dim3(32, 8)>>>(p_x1, ln2_g, ln2_b, p_yh);
    // 6) h1 = gelu(y @ w_fc1 + b_fc1) -> bf16
    gemm_bf16<<<dim3(HID / 128, M_TOT / 128), 256, GSMEM>>>(
        p_yh, p_wfc1h, b_fc1, nullptr, nullptr, p_h1h, M_TOT, HID, CH, 1);
    // 7) out = x1 + h1 @ w_fc2 + b_fc2 (fp32)
    gemm_bf16<<<dim3(CH / 128, M_TOT / 128), 256, GSMEM>>>(
        p_h1h, p_wfc2h, b_fc2, p_x1, out, nullptr, M_TOT, CH, HID, 2);
}